// round 6
// baseline (speedup 1.0000x reference)
#include <cuda_runtime.h>
#include <math.h>
#include <stdint.h>

#define N_NODES 50000
#define N_EDGES 800000
#define NFEAT   512
#define NHID    128
#define NCLASS  64

// Scratch (allocation-free)
__device__ float g_h0[(size_t)N_NODES * NHID];
__device__ float g_h1[(size_t)N_NODES * NHID];
__device__ uint16_t g_w1t_hi[NHID * NFEAT];   // W1^T hi bf16 [n][k]
__device__ uint16_t g_w1t_lo[NHID * NFEAT];   // W1^T lo bf16 [n][k]
__device__ uint16_t g_w2t_hi[NCLASS * NHID];  // W2^T hi bf16 [n][k]
__device__ uint16_t g_w2t_lo[NCLASS * NHID];  // W2^T lo bf16 [n][k]
__device__ int g_rowptr[N_NODES + 1];

// ---------------------------------------------------------------------------
// helpers
// ---------------------------------------------------------------------------
__device__ __forceinline__ uint32_t smem_u32(const void* p) {
    uint32_t a;
    asm("{ .reg .u64 t; cvta.to.shared.u64 t, %1; cvt.u32.u64 %0, t; }" : "=r"(a) : "l"(p));
    return a;
}
__device__ __forceinline__ uint32_t pack_bf16x2(float lo, float hi) {
    uint32_t r;
    asm("cvt.rn.bf16x2.f32 %0, %1, %2;" : "=r"(r) : "f"(hi), "f"(lo));
    return r;
}
__device__ __forceinline__ float bf_lo_f32(uint32_t p) { return __uint_as_float(p << 16); }
__device__ __forceinline__ float bf_hi_f32(uint32_t p) { return __uint_as_float(p & 0xFFFF0000u); }

__device__ __forceinline__ void mma_bf16(float* d, const uint32_t* a,
                                         uint32_t b0, uint32_t b1) {
    asm("mma.sync.aligned.m16n8k16.row.col.f32.bf16.bf16.f32 "
        "{%0,%1,%2,%3}, {%4,%5,%6,%7}, {%8,%9}, {%0,%1,%2,%3};"
        : "+f"(d[0]), "+f"(d[1]), "+f"(d[2]), "+f"(d[3])
        : "r"(a[0]), "r"(a[1]), "r"(a[2]), "r"(a[3]), "r"(b0), "r"(b1));
}
__device__ __forceinline__ void cp_async16(uint32_t dst, const void* src) {
    asm volatile("cp.async.cg.shared.global [%0], [%1], 16;" :: "r"(dst), "l"(src));
}
#define CP_COMMIT() asm volatile("cp.async.commit_group;" ::: "memory")
#define CP_WAIT0()  asm volatile("cp.async.wait_group 0;" ::: "memory")

// ---------------------------------------------------------------------------
// prep kernels
// ---------------------------------------------------------------------------
__global__ void prep_w1_kernel(const float* __restrict__ W1) {
    int idx = blockIdx.x * 256 + threadIdx.x;
    if (idx >= NHID * NFEAT / 2) return;
    int n = idx >> 8;
    int k2 = (idx & 255) * 2;
    float w0 = W1[(size_t)k2 * NHID + n];
    float w1 = W1[(size_t)(k2 + 1) * NHID + n];
    uint32_t ph = pack_bf16x2(w0, w1);
    uint32_t pl = pack_bf16x2(w0 - bf_lo_f32(ph), w1 - bf_hi_f32(ph));
    *(uint32_t*)&g_w1t_hi[n * NFEAT + k2] = ph;
    *(uint32_t*)&g_w1t_lo[n * NFEAT + k2] = pl;
}

__global__ void prep_w2_kernel(const float* __restrict__ W2) {
    int idx = blockIdx.x * 256 + threadIdx.x;
    if (idx >= NCLASS * NHID / 2) return;
    int n = idx >> 6;                // 64 pairs per n
    int k2 = (idx & 63) * 2;
    float w0 = W2[(size_t)k2 * NCLASS + n];
    float w1 = W2[(size_t)(k2 + 1) * NCLASS + n];
    uint32_t ph = pack_bf16x2(w0, w1);
    uint32_t pl = pack_bf16x2(w0 - bf_lo_f32(ph), w1 - bf_hi_f32(ph));
    *(uint32_t*)&g_w2t_hi[n * NHID + k2] = ph;
    *(uint32_t*)&g_w2t_lo[n * NHID + k2] = pl;
}

__global__ void rowptr_kernel(const int* __restrict__ rows) {
    int e = blockIdx.x * 256 + threadIdx.x;
    if (e >= N_EDGES) return;
    int r = rows[e];
    int rp = (e == 0) ? -1 : rows[e - 1];
    for (int q = rp + 1; q <= r; ++q) g_rowptr[q] = e;
    if (e == N_EDGES - 1)
        for (int q = r + 1; q <= N_NODES; ++q) g_rowptr[q] = N_EDGES;
}

// ---------------------------------------------------------------------------
// GEMM1 via mma.sync bf16 split, double-buffered + cp.async (unchanged R5).
// ---------------------------------------------------------------------------
#define LDA 72
#define SA_HI 0
#define SA_LO 9216
#define SB_HI 18432
#define SB_LO 27648
#define BUFE  36864
#define SMEM_G1_BYTES (2 * BUFE * 2)

__global__ __launch_bounds__(256, 1) void gemm1_mma_kernel(const float* __restrict__ x,
                                                           float* __restrict__ out)
{
    extern __shared__ uint16_t sm[];
    const uint32_t smb = smem_u32(sm);

    const int tid  = threadIdx.x;
    const int wid  = tid >> 5;
    const int lane = tid & 31;
    const int m0   = blockIdx.x * 128;
    const int wm = (wid >> 1) * 32;
    const int wn = (wid & 1) * 64;

    float acc[2][8][4];
#pragma unroll
    for (int i = 0; i < 2; i++)
#pragma unroll
        for (int j = 0; j < 8; j++)
#pragma unroll
            for (int q = 0; q < 4; q++) acc[i][j][q] = 0.f;

    const int arow = tid >> 1;
    const int ahalf = tid & 1;
    int rg = m0 + arow;
    if (rg >= N_NODES) rg = N_NODES - 1;
    const float* xrow = x + (size_t)rg * NFEAT + ahalf * 32;
    const uint16_t* bhrow = g_w1t_hi + (size_t)arow * NFEAT + ahalf * 32;
    const uint16_t* blrow = g_w1t_lo + (size_t)arow * NFEAT + ahalf * 32;
    const int dstA = arow * LDA + ahalf * 32;

    float4 xa[8];

#define COPY_B(c, buf) do {                                                   \
        uint32_t dh = smb + ((buf) * BUFE + SB_HI + dstA) * 2;                \
        uint32_t dl = smb + ((buf) * BUFE + SB_LO + dstA) * 2;                \
        _Pragma("unroll")                                                     \
        for (int j = 0; j < 4; ++j) {                                         \
            cp_async16(dh + j * 16, bhrow + (c) * 64 + j * 8);                \
            cp_async16(dl + j * 16, blrow + (c) * 64 + j * 8);                \
        }                                                                     \
        CP_COMMIT();                                                          \
    } while (0)

#define LOAD_A(c) do {                                                        \
        _Pragma("unroll")                                                     \
        for (int j = 0; j < 8; ++j)                                           \
            xa[j] = *(const float4*)(xrow + (c) * 64 + j * 4);                \
    } while (0)

#define CONV_STORE_A(buf) do {                                                \
        uint32_t H[16], L[16];                                                \
        _Pragma("unroll")                                                     \
        for (int j = 0; j < 8; ++j) {                                         \
            uint32_t p0 = pack_bf16x2(xa[j].x, xa[j].y);                      \
            uint32_t p1 = pack_bf16x2(xa[j].z, xa[j].w);                      \
            H[2*j]   = p0;                                                    \
            H[2*j+1] = p1;                                                    \
            L[2*j]   = pack_bf16x2(xa[j].x - bf_lo_f32(p0), xa[j].y - bf_hi_f32(p0)); \
            L[2*j+1] = pack_bf16x2(xa[j].z - bf_lo_f32(p1), xa[j].w - bf_hi_f32(p1)); \
        }                                                                     \
        uint16_t* dh = sm + (buf) * BUFE + SA_HI + dstA;                      \
        uint16_t* dl = sm + (buf) * BUFE + SA_LO + dstA;                      \
        _Pragma("unroll")                                                     \
        for (int j = 0; j < 4; ++j) {                                         \
            *(uint4*)(dh + j * 8) = *(uint4*)&H[j * 4];                       \
            *(uint4*)(dl + j * 8) = *(uint4*)&L[j * 4];                       \
        }                                                                     \
    } while (0)

    COPY_B(0, 0);
    LOAD_A(0);
    CONV_STORE_A(0);
    CP_WAIT0();
    __syncthreads();

    for (int c = 0; c < 8; ++c) {
        const int cur = c & 1, nxt = cur ^ 1;
        if (c < 7) { COPY_B(c + 1, nxt); LOAD_A(c + 1); }

        const uint16_t* base = sm + cur * BUFE;
#pragma unroll
        for (int ks = 0; ks < 4; ++ks) {
            const int kk = ks * 16;
            uint32_t a_hi[2][4], a_lo[2][4];
#pragma unroll
            for (int mt = 0; mt < 2; ++mt) {
                int r = wm + mt * 16 + (lane >> 2);
                int cc = kk + (lane & 3) * 2;
                a_hi[mt][0] = *(const uint32_t*)(base + SA_HI + r * LDA + cc);
                a_hi[mt][1] = *(const uint32_t*)(base + SA_HI + (r + 8) * LDA + cc);
                a_hi[mt][2] = *(const uint32_t*)(base + SA_HI + r * LDA + cc + 8);
                a_hi[mt][3] = *(const uint32_t*)(base + SA_HI + (r + 8) * LDA + cc + 8);
                a_lo[mt][0] = *(const uint32_t*)(base + SA_LO + r * LDA + cc);
                a_lo[mt][1] = *(const uint32_t*)(base + SA_LO + (r + 8) * LDA + cc);
                a_lo[mt][2] = *(const uint32_t*)(base + SA_LO + r * LDA + cc + 8);
                a_lo[mt][3] = *(const uint32_t*)(base + SA_LO + (r + 8) * LDA + cc + 8);
            }
#pragma unroll
            for (int nt = 0; nt < 8; ++nt) {
                int n = wn + nt * 8 + (lane >> 2);
                int kq = kk + (lane & 3) * 2;
                uint32_t bh0 = *(const uint32_t*)(base + SB_HI + n * LDA + kq);
                uint32_t bh1 = *(const uint32_t*)(base + SB_HI + n * LDA + kq + 8);
                uint32_t bl0 = *(const uint32_t*)(base + SB_LO + n * LDA + kq);
                uint32_t bl1 = *(const uint32_t*)(base + SB_LO + n * LDA + kq + 8);
#pragma unroll
                for (int mt = 0; mt < 2; ++mt) {
                    mma_bf16(acc[mt][nt], a_hi[mt], bh0, bh1);
                    mma_bf16(acc[mt][nt], a_hi[mt], bl0, bl1);
                    mma_bf16(acc[mt][nt], a_lo[mt], bh0, bh1);
                }
            }
        }

        if (c < 7) { CONV_STORE_A(nxt); CP_WAIT0(); }
        __syncthreads();
    }

#pragma unroll
    for (int mt = 0; mt < 2; ++mt) {
        int r0 = m0 + wm + mt * 16 + (lane >> 2);
        int r1 = r0 + 8;
#pragma unroll
        for (int nt = 0; nt < 8; ++nt) {
            int cc = wn + nt * 8 + (lane & 3) * 2;
            if (r0 < N_NODES)
                *(float2*)(out + (size_t)r0 * NHID + cc) = make_float2(acc[mt][nt][0], acc[mt][nt][1]);
            if (r1 < N_NODES)
                *(float2*)(out + (size_t)r1 * NHID + cc) = make_float2(acc[mt][nt][2], acc[mt][nt][3]);
        }
    }
}

// ---------------------------------------------------------------------------
// SpMM: warp per row, row_ptr, 8-edge unroll.
// ---------------------------------------------------------------------------
template <bool RELU>
__global__ __launch_bounds__(256) void spmm_kernel(const int* __restrict__ cols,
                                                   const float* __restrict__ vals,
                                                   const float* __restrict__ hin,
                                                   const float* __restrict__ bias,
                                                   float* __restrict__ hout)
{
    const int gw   = (blockIdx.x * blockDim.x + threadIdx.x) >> 5;
    const int lane = threadIdx.x & 31;
    if (gw >= N_NODES) return;

    const int start = g_rowptr[gw];
    const int end   = g_rowptr[gw + 1];

    float ax = 0.f, ay = 0.f, az = 0.f, aw = 0.f;
    int e = start;
    for (; e + 8 <= end; e += 8) {
        int   c[8];
        float v[8];
#pragma unroll
        for (int j = 0; j < 8; ++j) { c[j] = cols[e + j]; v[j] = vals[e + j]; }
        float4 hh[8];
#pragma unroll
        for (int j = 0; j < 8; ++j)
            hh[j] = *(const float4*)(hin + (size_t)c[j] * NHID + lane * 4);
#pragma unroll
        for (int j = 0; j < 8; ++j) {
            ax = fmaf(v[j], hh[j].x, ax); ay = fmaf(v[j], hh[j].y, ay);
            az = fmaf(v[j], hh[j].z, az); aw = fmaf(v[j], hh[j].w, aw);
        }
    }
    for (; e < end; ++e) {
        int   c0 = cols[e];
        float v0 = vals[e];
        float4 h0 = *(const float4*)(hin + (size_t)c0 * NHID + lane * 4);
        ax = fmaf(v0, h0.x, ax); ay = fmaf(v0, h0.y, ay);
        az = fmaf(v0, h0.z, az); aw = fmaf(v0, h0.w, aw);
    }
    if (RELU) {
        float4 b = ((const float4*)bias)[lane];
        ax = fmaxf(ax + b.x, 0.f); ay = fmaxf(ay + b.y, 0.f);
        az = fmaxf(az + b.z, 0.f); aw = fmaxf(aw + b.w, 0.f);
    }
    *(float4*)(hout + (size_t)gw * NHID + lane * 4) = make_float4(ax, ay, az, aw);
}

// ---------------------------------------------------------------------------
// GEMM2 via mma.sync bf16 split + fused bias + log_softmax.
// CTA: 64 rows x 64 cols, 128 threads (4 warps; warp = 16 rows). K = 128.
// smem pitch 136 (same conflict-free class as 72: 68 = 36 = 4 mod 32).
// ---------------------------------------------------------------------------
#define LDH 136
#define G2_SHH 0
#define G2_SHL 8704
#define G2_SWH 17408
#define G2_SWL 26112
#define SMEM_G2_BYTES (34816 * 2)

__global__ __launch_bounds__(128) void gemm2_mma_kernel(const float* __restrict__ h,
                                                        const float* __restrict__ b2,
                                                        float* __restrict__ out)
{
    extern __shared__ uint16_t s2[];

    const int tid  = threadIdx.x;
    const int lane = tid & 31;
    const int wid  = tid >> 5;
    const int r0   = blockIdx.x * 64;

    // ---- load + convert H tile: 64 rows x 128 k ----
    const int row = tid >> 1, half = tid & 1;
    int rg = r0 + row;
    if (rg >= N_NODES) rg = N_NODES - 1;
    const float* hrow = h + (size_t)rg * NHID + half * 64;
#pragma unroll
    for (int g = 0; g < 2; ++g) {
        uint32_t H[16], L[16];
#pragma unroll
        for (int j = 0; j < 8; ++j) {
            float4 v = *(const float4*)(hrow + g * 32 + j * 4);
            uint32_t p0 = pack_bf16x2(v.x, v.y);
            uint32_t p1 = pack_bf16x2(v.z, v.w);
            H[2 * j]     = p0;
            H[2 * j + 1] = p1;
            L[2 * j]     = pack_bf16x2(v.x - bf_lo_f32(p0), v.y - bf_hi_f32(p0));
            L[2 * j + 1] = pack_bf16x2(v.z - bf_lo_f32(p1), v.w - bf_hi_f32(p1));
        }
        uint16_t* dh = s2 + G2_SHH + row * LDH + half * 64 + g * 32;
        uint16_t* dl = s2 + G2_SHL + row * LDH + half * 64 + g * 32;
#pragma unroll
        for (int j = 0; j < 4; ++j) {
            *(uint4*)(dh + j * 8) = *(uint4*)&H[j * 4];
            *(uint4*)(dl + j * 8) = *(uint4*)&L[j * 4];
        }
    }

    // ---- copy W2^T hi/lo: 64 n x 128 k ----
    {
        const int n = tid >> 1;     // 0..63
        const uint16_t* wh = g_w2t_hi + n * NHID + half * 64;
        const uint16_t* wl = g_w2t_lo + n * NHID + half * 64;
        uint16_t* dh = s2 + G2_SWH + n * LDH + half * 64;
        uint16_t* dl = s2 + G2_SWL + n * LDH + half * 64;
#pragma unroll
        for (int j = 0; j < 8; ++j) {
            *(uint4*)(dh + j * 8) = *(const uint4*)(wh + j * 8);
            *(uint4*)(dl + j * 8) = *(const uint4*)(wl + j * 8);
        }
    }
    __syncthreads();

    // ---- MMA: warp wid covers rows [wid*16, wid*16+16), all 64 cols ----
    float acc[8][4];
#pragma unroll
    for (int nt = 0; nt < 8; ++nt)
#pragma unroll
        for (int q = 0; q < 4; ++q) acc[nt][q] = 0.f;

    const int wr = wid * 16;
#pragma unroll
    for (int ks = 0; ks < 8; ++ks) {
        const int kk = ks * 16;
        const int r  = wr + (lane >> 2);
        const int cc = kk + (lane & 3) * 2;
        uint32_t a_hi[4], a_lo[4];
        a_hi[0] = *(const uint32_t*)(s2 + G2_SHH + r * LDH + cc);
        a_hi[1] = *(const uint32_t*)(s2 + G2_SHH + (r + 8) * LDH + cc);
        a_hi[2] = *(const uint32_t*)(s2 + G2_SHH + r * LDH + cc + 8);
        a_hi[3] = *(const uint32_t*)(s2 + G2_SHH + (r + 8) * LDH + cc + 8);
        a_lo[0] = *(const uint32_t*)(s2 + G2_SHL + r * LDH + cc);
        a_lo[1] = *(const uint32_t*)(s2 + G2_SHL + (r + 8) * LDH + cc);
        a_lo[2] = *(const uint32_t*)(s2 + G2_SHL + r * LDH + cc + 8);
        a_lo[3] = *(const uint32_t*)(s2 + G2_SHL + (r + 8) * LDH + cc + 8);
#pragma unroll
        for (int nt = 0; nt < 8; ++nt) {
            int n  = nt * 8 + (lane >> 2);
            int kq = kk + (lane & 3) * 2;
            uint32_t bh0 = *(const uint32_t*)(s2 + G2_SWH + n * LDH + kq);
            uint32_t bh1 = *(const uint32_t*)(s2 + G2_SWH + n * LDH + kq + 8);
            uint32_t bl0 = *(const uint32_t*)(s2 + G2_SWL + n * LDH + kq);
            uint32_t bl1 = *(const uint32_t*)(s2 + G2_SWL + n * LDH + kq + 8);
            mma_bf16(acc[nt], a_hi, bh0, bh1);
            mma_bf16(acc[nt], a_hi, bl0, bl1);
            mma_bf16(acc[nt], a_lo, bh0, bh1);
        }
    }

    // ---- bias ----
#pragma unroll
    for (int nt = 0; nt < 8; ++nt) {
        int c = nt * 8 + (lane & 3) * 2;
        float bb0 = b2[c], bb1 = b2[c + 1];
        acc[nt][0] += bb0; acc[nt][1] += bb1;
        acc[nt][2] += bb0; acc[nt][3] += bb1;
    }

    // ---- log-softmax: rows r (acc[.][0,1]) and r+8 (acc[.][2,3]);
    //      quad lanes (xor 1, 2) jointly cover all 64 cols of a row ----
    float m0 = -1e30f, m1 = -1e30f;
#pragma unroll
    for (int nt = 0; nt < 8; ++nt) {
        m0 = fmaxf(m0, fmaxf(acc[nt][0], acc[nt][1]));
        m1 = fmaxf(m1, fmaxf(acc[nt][2], acc[nt][3]));
    }
    m0 = fmaxf(m0, __shfl_xor_sync(0xffffffffu, m0, 1));
    m0 = fmaxf(m0, __shfl_xor_sync(0xffffffffu, m0, 2));
    m1 = fmaxf(m1, __shfl_xor_sync(0xffffffffu, m1, 1));
    m1 = fmaxf(m1, __shfl_xor_sync(0xffffffffu, m1, 2));

    float s0 = 0.f, s1 = 0.f;
#pragma unroll
    for (int nt = 0; nt < 8; ++nt) {
        s0 += expf(acc[nt][0] - m0) + expf(acc[nt][1] - m0);
        s1 += expf(acc[nt][2] - m1) + expf(acc[nt][3] - m1);
    }
    s0 += __shfl_xor_sync(0xffffffffu, s0, 1);
    s0 += __shfl_xor_sync(0xffffffffu, s0, 2);
    s1 += __shfl_xor_sync(0xffffffffu, s1, 1);
    s1 += __shfl_xor_sync(0xffffffffu, s1, 2);
    const float lse0 = m0 + logf(s0);
    const float lse1 = m1 + logf(s1);

    const int row0 = r0 + wr + (lane >> 2);
    const int row1 = row0 + 8;
#pragma unroll
    for (int nt = 0; nt < 8; ++nt) {
        int c = nt * 8 + (lane & 3) * 2;
        if (row0 < N_NODES)
            *(float2*)(out + (size_t)row0 * NCLASS + c) =
                make_float2(acc[nt][0] - lse0, acc[nt][1] - lse0);
        if (row1 < N_NODES)
            *(float2*)(out + (size_t)row1 * NCLASS + c) =
                make_float2(acc[nt][2] - lse1, acc[nt][3] - lse1);
    }
}

// ---------------------------------------------------------------------------
extern "C" void kernel_launch(void* const* d_in, const int* in_sizes, int n_in,
                              void* d_out, int out_size)
{
    const float* x    = (const float*)d_in[0];
    const int*   rows = (const int*)  d_in[1];
    const int*   cols = (const int*)  d_in[2];
    const float* vals = (const float*)d_in[3];
    const float* W1   = (const float*)d_in[4];
    const float* b1   = (const float*)d_in[5];
    const float* W2   = (const float*)d_in[6];
    const float* b2   = (const float*)d_in[7];
    float* out = (float*)d_out;

    float *h0, *h1;
    cudaGetSymbolAddress((void**)&h0, g_h0);
    cudaGetSymbolAddress((void**)&h1, g_h1);

    cudaFuncSetAttribute(gemm1_mma_kernel, cudaFuncAttributeMaxDynamicSharedMemorySize, SMEM_G1_BYTES);
    cudaFuncSetAttribute(gemm2_mma_kernel, cudaFuncAttributeMaxDynamicSharedMemorySize, SMEM_G2_BYTES);

    // 0) prep: W1^T, W2^T bf16 hi/lo, row_ptr
    prep_w1_kernel<<<(NHID * NFEAT / 2 + 255) / 256, 256>>>(W1);
    prep_w2_kernel<<<(NCLASS * NHID / 2 + 255) / 256, 256>>>(W2);
    rowptr_kernel<<<(N_EDGES + 255) / 256, 256>>>(rows);

    // 1) h0 = X @ W1
    gemm1_mma_kernel<<<(N_NODES + 127) / 128, 256, SMEM_G1_BYTES>>>(x, h0);

    // 2) h1 = relu(A @ h0 + b1)
    const int spmm_blocks = (N_NODES * 32 + 255) / 256;
    spmm_kernel<true><<<spmm_blocks, 256>>>(cols, vals, h0, b1, h1);

    // 3) h0 <- A @ h1
    spmm_kernel<false><<<spmm_blocks, 256>>>(cols, vals, h1, b1, h0);

    // 4) out = logsoftmax(h0 @ W2 + b2), fused in-fragment
    gemm2_mma_kernel<<<(N_NODES + 63) / 64, 128, SMEM_G2_BYTES>>>(h0, b2, out);
}

// round 7
// speedup vs baseline: 1.0247x; 1.0247x over previous
#include <cuda_runtime.h>
#include <math.h>
#include <stdint.h>

#define N_NODES 50000
#define N_EDGES 800000
#define NFEAT   512
#define NHID    128
#define NCLASS  64

// Scratch (allocation-free)
__device__ float g_h0[(size_t)N_NODES * NHID];
__device__ float g_h1[(size_t)N_NODES * NHID];
__device__ uint16_t g_w1t_hi[NHID * NFEAT];   // W1^T hi bf16 [n][k]
__device__ uint16_t g_w1t_lo[NHID * NFEAT];   // W1^T lo bf16 [n][k]
__device__ uint16_t g_w2t_hi[NCLASS * NHID];  // W2^T hi bf16 [n][k]
__device__ uint16_t g_w2t_lo[NCLASS * NHID];  // W2^T lo bf16 [n][k]
__device__ int g_rowptr[N_NODES + 1];

// ---------------------------------------------------------------------------
// helpers
// ---------------------------------------------------------------------------
__device__ __forceinline__ uint32_t smem_u32(const void* p) {
    uint32_t a;
    asm("{ .reg .u64 t; cvta.to.shared.u64 t, %1; cvt.u32.u64 %0, t; }" : "=r"(a) : "l"(p));
    return a;
}
__device__ __forceinline__ uint32_t pack_bf16x2(float lo, float hi) {
    uint32_t r;
    asm("cvt.rn.bf16x2.f32 %0, %1, %2;" : "=r"(r) : "f"(hi), "f"(lo));
    return r;
}
__device__ __forceinline__ float bf_lo_f32(uint32_t p) { return __uint_as_float(p << 16); }
__device__ __forceinline__ float bf_hi_f32(uint32_t p) { return __uint_as_float(p & 0xFFFF0000u); }

__device__ __forceinline__ void mma_bf16(float* d, const uint32_t* a,
                                         uint32_t b0, uint32_t b1) {
    asm("mma.sync.aligned.m16n8k16.row.col.f32.bf16.bf16.f32 "
        "{%0,%1,%2,%3}, {%4,%5,%6,%7}, {%8,%9}, {%0,%1,%2,%3};"
        : "+f"(d[0]), "+f"(d[1]), "+f"(d[2]), "+f"(d[3])
        : "r"(a[0]), "r"(a[1]), "r"(a[2]), "r"(a[3]), "r"(b0), "r"(b1));
}
__device__ __forceinline__ void cp_async16(uint32_t dst, const void* src) {
    asm volatile("cp.async.cg.shared.global [%0], [%1], 16;" :: "r"(dst), "l"(src));
}
#define CP_COMMIT() asm volatile("cp.async.commit_group;" ::: "memory")
#define CP_WAIT0()  asm volatile("cp.async.wait_group 0;" ::: "memory")

// ---------------------------------------------------------------------------
// prep kernels
// ---------------------------------------------------------------------------
__global__ void prep_w1_kernel(const float* __restrict__ W1) {
    int idx = blockIdx.x * 256 + threadIdx.x;
    if (idx >= NHID * NFEAT / 2) return;
    int n = idx >> 8;
    int k2 = (idx & 255) * 2;
    float w0 = W1[(size_t)k2 * NHID + n];
    float w1 = W1[(size_t)(k2 + 1) * NHID + n];
    uint32_t ph = pack_bf16x2(w0, w1);
    uint32_t pl = pack_bf16x2(w0 - bf_lo_f32(ph), w1 - bf_hi_f32(ph));
    *(uint32_t*)&g_w1t_hi[n * NFEAT + k2] = ph;
    *(uint32_t*)&g_w1t_lo[n * NFEAT + k2] = pl;
}

__global__ void prep_w2_kernel(const float* __restrict__ W2) {
    int idx = blockIdx.x * 256 + threadIdx.x;
    if (idx >= NCLASS * NHID / 2) return;
    int n = idx >> 6;
    int k2 = (idx & 63) * 2;
    float w0 = W2[(size_t)k2 * NCLASS + n];
    float w1 = W2[(size_t)(k2 + 1) * NCLASS + n];
    uint32_t ph = pack_bf16x2(w0, w1);
    uint32_t pl = pack_bf16x2(w0 - bf_lo_f32(ph), w1 - bf_hi_f32(ph));
    *(uint32_t*)&g_w2t_hi[n * NHID + k2] = ph;
    *(uint32_t*)&g_w2t_lo[n * NHID + k2] = pl;
}

__global__ void rowptr_kernel(const int* __restrict__ rows) {
    int e = blockIdx.x * 256 + threadIdx.x;
    if (e >= N_EDGES) return;
    int r = rows[e];
    int rp = (e == 0) ? -1 : rows[e - 1];
    for (int q = rp + 1; q <= r; ++q) g_rowptr[q] = e;
    if (e == N_EDGES - 1)
        for (int q = r + 1; q <= N_NODES; ++q) g_rowptr[q] = N_EDGES;
}

// ---------------------------------------------------------------------------
// GEMM1 via mma.sync bf16 split. BK=32, double-buffered, 2 CTAs/SM.
// CTA 128x128, 8 warps (4M x 2N), warp tile 32x64. Pitch 40 (conflict-free).
// Per buffer: A_hi|A_lo|B_hi|B_lo, each 128x40 bf16 -> 40960 B; x2 = 80 KB.
// ---------------------------------------------------------------------------
#define LDA   40
#define SA_HI 0
#define SA_LO 5120
#define SB_HI 10240
#define SB_LO 15360
#define BUFE  20480
#define SMEM_G1_BYTES (2 * BUFE * 2)   // 81920

__global__ __launch_bounds__(256, 2) void gemm1_mma_kernel(const float* __restrict__ x,
                                                           float* __restrict__ out)
{
    extern __shared__ uint16_t sm[];
    const uint32_t smb = smem_u32(sm);

    const int tid  = threadIdx.x;
    const int wid  = tid >> 5;
    const int lane = tid & 31;
    const int m0   = blockIdx.x * 128;
    const int wm = (wid >> 1) * 32;
    const int wn = (wid & 1) * 64;

    float acc[2][8][4];
#pragma unroll
    for (int i = 0; i < 2; i++)
#pragma unroll
        for (int j = 0; j < 8; j++)
#pragma unroll
            for (int q = 0; q < 4; q++) acc[i][j][q] = 0.f;

    // row-per-lane mapping: lanes cover consecutive rows (conflict-free STS)
    const int arow  = tid & 127;      // 0..127
    const int ahalf = tid >> 7;       // 0/1 -> 16 k each
    int rg = m0 + arow;
    if (rg >= N_NODES) rg = N_NODES - 1;
    const float* xrow = x + (size_t)rg * NFEAT + ahalf * 16;
    const uint16_t* bhrow = g_w1t_hi + (size_t)arow * NFEAT + ahalf * 16;
    const uint16_t* blrow = g_w1t_lo + (size_t)arow * NFEAT + ahalf * 16;
    const int dstA = arow * LDA + ahalf * 16;

    float4 xa[4];

#define COPY_B(c, buf) do {                                                   \
        uint32_t dh = smb + ((buf) * BUFE + SB_HI + dstA) * 2;                \
        uint32_t dl = smb + ((buf) * BUFE + SB_LO + dstA) * 2;                \
        _Pragma("unroll")                                                     \
        for (int j = 0; j < 2; ++j) {                                         \
            cp_async16(dh + j * 16, bhrow + (c) * 32 + j * 8);                \
            cp_async16(dl + j * 16, blrow + (c) * 32 + j * 8);                \
        }                                                                     \
        CP_COMMIT();                                                          \
    } while (0)

#define LOAD_A(c) do {                                                        \
        _Pragma("unroll")                                                     \
        for (int j = 0; j < 4; ++j)                                           \
            xa[j] = *(const float4*)(xrow + (c) * 32 + j * 4);                \
    } while (0)

#define CONV_STORE_A(buf) do {                                                \
        uint32_t H[8], L[8];                                                  \
        _Pragma("unroll")                                                     \
        for (int j = 0; j < 4; ++j) {                                         \
            uint32_t p0 = pack_bf16x2(xa[j].x, xa[j].y);                      \
            uint32_t p1 = pack_bf16x2(xa[j].z, xa[j].w);                      \
            H[2*j]   = p0;                                                    \
            H[2*j+1] = p1;                                                    \
            L[2*j]   = pack_bf16x2(xa[j].x - bf_lo_f32(p0), xa[j].y - bf_hi_f32(p0)); \
            L[2*j+1] = pack_bf16x2(xa[j].z - bf_lo_f32(p1), xa[j].w - bf_hi_f32(p1)); \
        }                                                                     \
        uint16_t* dh = sm + (buf) * BUFE + SA_HI + dstA;                      \
        uint16_t* dl = sm + (buf) * BUFE + SA_LO + dstA;                      \
        _Pragma("unroll")                                                     \
        for (int j = 0; j < 2; ++j) {                                         \
            *(uint4*)(dh + j * 8) = *(uint4*)&H[j * 4];                       \
            *(uint4*)(dl + j * 8) = *(uint4*)&L[j * 4];                       \
        }                                                                     \
    } while (0)

    COPY_B(0, 0);
    LOAD_A(0);
    CONV_STORE_A(0);
    CP_WAIT0();
    __syncthreads();

    for (int c = 0; c < 16; ++c) {
        const int cur = c & 1, nxt = cur ^ 1;
        if (c < 15) { COPY_B(c + 1, nxt); LOAD_A(c + 1); }

        const uint16_t* base = sm + cur * BUFE;
#pragma unroll
        for (int ks = 0; ks < 2; ++ks) {
            const int kk = ks * 16;
            uint32_t a_hi[2][4], a_lo[2][4];
#pragma unroll
            for (int mt = 0; mt < 2; ++mt) {
                int r = wm + mt * 16 + (lane >> 2);
                int cc = kk + (lane & 3) * 2;
                a_hi[mt][0] = *(const uint32_t*)(base + SA_HI + r * LDA + cc);
                a_hi[mt][1] = *(const uint32_t*)(base + SA_HI + (r + 8) * LDA + cc);
                a_hi[mt][2] = *(const uint32_t*)(base + SA_HI + r * LDA + cc + 8);
                a_hi[mt][3] = *(const uint32_t*)(base + SA_HI + (r + 8) * LDA + cc + 8);
                a_lo[mt][0] = *(const uint32_t*)(base + SA_LO + r * LDA + cc);
                a_lo[mt][1] = *(const uint32_t*)(base + SA_LO + (r + 8) * LDA + cc);
                a_lo[mt][2] = *(const uint32_t*)(base + SA_LO + r * LDA + cc + 8);
                a_lo[mt][3] = *(const uint32_t*)(base + SA_LO + (r + 8) * LDA + cc + 8);
            }
#pragma unroll
            for (int nt = 0; nt < 8; ++nt) {
                int n = wn + nt * 8 + (lane >> 2);
                int kq = kk + (lane & 3) * 2;
                uint32_t bh0 = *(const uint32_t*)(base + SB_HI + n * LDA + kq);
                uint32_t bh1 = *(const uint32_t*)(base + SB_HI + n * LDA + kq + 8);
                uint32_t bl0 = *(const uint32_t*)(base + SB_LO + n * LDA + kq);
                uint32_t bl1 = *(const uint32_t*)(base + SB_LO + n * LDA + kq + 8);
#pragma unroll
                for (int mt = 0; mt < 2; ++mt) {
                    mma_bf16(acc[mt][nt], a_hi[mt], bh0, bh1);
                    mma_bf16(acc[mt][nt], a_hi[mt], bl0, bl1);
                    mma_bf16(acc[mt][nt], a_lo[mt], bh0, bh1);
                }
            }
        }

        if (c < 15) { CONV_STORE_A(nxt); CP_WAIT0(); }
        __syncthreads();
    }

#pragma unroll
    for (int mt = 0; mt < 2; ++mt) {
        int r0 = m0 + wm + mt * 16 + (lane >> 2);
        int r1 = r0 + 8;
#pragma unroll
        for (int nt = 0; nt < 8; ++nt) {
            int cc = wn + nt * 8 + (lane & 3) * 2;
            if (r0 < N_NODES)
                *(float2*)(out + (size_t)r0 * NHID + cc) = make_float2(acc[mt][nt][0], acc[mt][nt][1]);
            if (r1 < N_NODES)
                *(float2*)(out + (size_t)r1 * NHID + cc) = make_float2(acc[mt][nt][2], acc[mt][nt][3]);
        }
    }
}

// ---------------------------------------------------------------------------
// SpMM: warp per row, row_ptr, 4-edge unroll (measured-best config).
// ---------------------------------------------------------------------------
template <bool RELU>
__global__ __launch_bounds__(256) void spmm_kernel(const int* __restrict__ cols,
                                                   const float* __restrict__ vals,
                                                   const float* __restrict__ hin,
                                                   const float* __restrict__ bias,
                                                   float* __restrict__ hout)
{
    const int gw   = (blockIdx.x * blockDim.x + threadIdx.x) >> 5;
    const int lane = threadIdx.x & 31;
    if (gw >= N_NODES) return;

    const int start = g_rowptr[gw];
    const int end   = g_rowptr[gw + 1];

    float ax = 0.f, ay = 0.f, az = 0.f, aw = 0.f;
    int e = start;
    for (; e + 4 <= end; e += 4) {
        int   c0 = cols[e],     c1 = cols[e + 1], c2 = cols[e + 2], c3 = cols[e + 3];
        float v0 = vals[e],     v1 = vals[e + 1], v2 = vals[e + 2], v3 = vals[e + 3];
        float4 h0 = *(const float4*)(hin + (size_t)c0 * NHID + lane * 4);
        float4 h1 = *(const float4*)(hin + (size_t)c1 * NHID + lane * 4);
        float4 h2 = *(const float4*)(hin + (size_t)c2 * NHID + lane * 4);
        float4 h3 = *(const float4*)(hin + (size_t)c3 * NHID + lane * 4);
        ax = fmaf(v0, h0.x, ax); ay = fmaf(v0, h0.y, ay);
        az = fmaf(v0, h0.z, az); aw = fmaf(v0, h0.w, aw);
        ax = fmaf(v1, h1.x, ax); ay = fmaf(v1, h1.y, ay);
        az = fmaf(v1, h1.z, az); aw = fmaf(v1, h1.w, aw);
        ax = fmaf(v2, h2.x, ax); ay = fmaf(v2, h2.y, ay);
        az = fmaf(v2, h2.z, az); aw = fmaf(v2, h2.w, aw);
        ax = fmaf(v3, h3.x, ax); ay = fmaf(v3, h3.y, ay);
        az = fmaf(v3, h3.z, az); aw = fmaf(v3, h3.w, aw);
    }
    for (; e < end; ++e) {
        int   c0 = cols[e];
        float v0 = vals[e];
        float4 h0 = *(const float4*)(hin + (size_t)c0 * NHID + lane * 4);
        ax = fmaf(v0, h0.x, ax); ay = fmaf(v0, h0.y, ay);
        az = fmaf(v0, h0.z, az); aw = fmaf(v0, h0.w, aw);
    }
    if (RELU) {
        float4 b = ((const float4*)bias)[lane];
        ax = fmaxf(ax + b.x, 0.f); ay = fmaxf(ay + b.y, 0.f);
        az = fmaxf(az + b.z, 0.f); aw = fmaxf(aw + b.w, 0.f);
    }
    *(float4*)(hout + (size_t)gw * NHID + lane * 4) = make_float4(ax, ay, az, aw);
}

// ---------------------------------------------------------------------------
// GEMM2 via mma.sync bf16 split + fused bias + log_softmax. (R6, kept)
// ---------------------------------------------------------------------------
#define LDH 136
#define G2_SHH 0
#define G2_SHL 8704
#define G2_SWH 17408
#define G2_SWL 26112
#define SMEM_G2_BYTES (34816 * 2)

__global__ __launch_bounds__(128) void gemm2_mma_kernel(const float* __restrict__ h,
                                                        const float* __restrict__ b2,
                                                        float* __restrict__ out)
{
    extern __shared__ uint16_t s2[];

    const int tid  = threadIdx.x;
    const int lane = tid & 31;
    const int wid  = tid >> 5;
    const int r0   = blockIdx.x * 64;

    const int row = tid >> 1, half = tid & 1;
    int rg = r0 + row;
    if (rg >= N_NODES) rg = N_NODES - 1;
    const float* hrow = h + (size_t)rg * NHID + half * 64;
#pragma unroll
    for (int g = 0; g < 2; ++g) {
        uint32_t H[16], L[16];
#pragma unroll
        for (int j = 0; j < 8; ++j) {
            float4 v = *(const float4*)(hrow + g * 32 + j * 4);
            uint32_t p0 = pack_bf16x2(v.x, v.y);
            uint32_t p1 = pack_bf16x2(v.z, v.w);
            H[2 * j]     = p0;
            H[2 * j + 1] = p1;
            L[2 * j]     = pack_bf16x2(v.x - bf_lo_f32(p0), v.y - bf_hi_f32(p0));
            L[2 * j + 1] = pack_bf16x2(v.z - bf_lo_f32(p1), v.w - bf_hi_f32(p1));
        }
        uint16_t* dh = s2 + G2_SHH + row * LDH + half * 64 + g * 32;
        uint16_t* dl = s2 + G2_SHL + row * LDH + half * 64 + g * 32;
#pragma unroll
        for (int j = 0; j < 4; ++j) {
            *(uint4*)(dh + j * 8) = *(uint4*)&H[j * 4];
            *(uint4*)(dl + j * 8) = *(uint4*)&L[j * 4];
        }
    }

    {
        const int n = tid >> 1;
        const uint16_t* wh = g_w2t_hi + n * NHID + half * 64;
        const uint16_t* wl = g_w2t_lo + n * NHID + half * 64;
        uint16_t* dh = s2 + G2_SWH + n * LDH + half * 64;
        uint16_t* dl = s2 + G2_SWL + n * LDH + half * 64;
#pragma unroll
        for (int j = 0; j < 8; ++j) {
            *(uint4*)(dh + j * 8) = *(const uint4*)(wh + j * 8);
            *(uint4*)(dl + j * 8) = *(const uint4*)(wl + j * 8);
        }
    }
    __syncthreads();

    float acc[8][4];
#pragma unroll
    for (int nt = 0; nt < 8; ++nt)
#pragma unroll
        for (int q = 0; q < 4; ++q) acc[nt][q] = 0.f;

    const int wr = wid * 16;
#pragma unroll
    for (int ks = 0; ks < 8; ++ks) {
        const int kk = ks * 16;
        const int r  = wr + (lane >> 2);
        const int cc = kk + (lane & 3) * 2;
        uint32_t a_hi[4], a_lo[4];
        a_hi[0] = *(const uint32_t*)(s2 + G2_SHH + r * LDH + cc);
        a_hi[1] = *(const uint32_t*)(s2 + G2_SHH + (r + 8) * LDH + cc);
        a_hi[2] = *(const uint32_t*)(s2 + G2_SHH + r * LDH + cc + 8);
        a_hi[3] = *(const uint32_t*)(s2 + G2_SHH + (r + 8) * LDH + cc + 8);
        a_lo[0] = *(const uint32_t*)(s2 + G2_SHL + r * LDH + cc);
        a_lo[1] = *(const uint32_t*)(s2 + G2_SHL + (r + 8) * LDH + cc);
        a_lo[2] = *(const uint32_t*)(s2 + G2_SHL + r * LDH + cc + 8);
        a_lo[3] = *(const uint32_t*)(s2 + G2_SHL + (r + 8) * LDH + cc + 8);
#pragma unroll
        for (int nt = 0; nt < 8; ++nt) {
            int n  = nt * 8 + (lane >> 2);
            int kq = kk + (lane & 3) * 2;
            uint32_t bh0 = *(const uint32_t*)(s2 + G2_SWH + n * LDH + kq);
            uint32_t bh1 = *(const uint32_t*)(s2 + G2_SWH + n * LDH + kq + 8);
            uint32_t bl0 = *(const uint32_t*)(s2 + G2_SWL + n * LDH + kq);
            uint32_t bl1 = *(const uint32_t*)(s2 + G2_SWL + n * LDH + kq + 8);
            mma_bf16(acc[nt], a_hi, bh0, bh1);
            mma_bf16(acc[nt], a_hi, bl0, bl1);
            mma_bf16(acc[nt], a_lo, bh0, bh1);
        }
    }

#pragma unroll
    for (int nt = 0; nt < 8; ++nt) {
        int c = nt * 8 + (lane & 3) * 2;
        float bb0 = b2[c], bb1 = b2[c + 1];
        acc[nt][0] += bb0; acc[nt][1] += bb1;
        acc[nt][2] += bb0; acc[nt][3] += bb1;
    }

    float m0 = -1e30f, m1 = -1e30f;
#pragma unroll
    for (int nt = 0; nt < 8; ++nt) {
        m0 = fmaxf(m0, fmaxf(acc[nt][0], acc[nt][1]));
        m1 = fmaxf(m1, fmaxf(acc[nt][2], acc[nt][3]));
    }
    m0 = fmaxf(m0, __shfl_xor_sync(0xffffffffu, m0, 1));
    m0 = fmaxf(m0, __shfl_xor_sync(0xffffffffu, m0, 2));
    m1 = fmaxf(m1, __shfl_xor_sync(0xffffffffu, m1, 1));
    m1 = fmaxf(m1, __shfl_xor_sync(0xffffffffu, m1, 2));

    float s0 = 0.f, s1 = 0.f;
#pragma unroll
    for (int nt = 0; nt < 8; ++nt) {
        s0 += expf(acc[nt][0] - m0) + expf(acc[nt][1] - m0);
        s1 += expf(acc[nt][2] - m1) + expf(acc[nt][3] - m1);
    }
    s0 += __shfl_xor_sync(0xffffffffu, s0, 1);
    s0 += __shfl_xor_sync(0xffffffffu, s0, 2);
    s1 += __shfl_xor_sync(0xffffffffu, s1, 1);
    s1 += __shfl_xor_sync(0xffffffffu, s1, 2);
    const float lse0 = m0 + logf(s0);
    const float lse1 = m1 + logf(s1);

    const int row0 = r0 + wr + (lane >> 2);
    const int row1 = row0 + 8;
#pragma unroll
    for (int nt = 0; nt < 8; ++nt) {
        int c = nt * 8 + (lane & 3) * 2;
        if (row0 < N_NODES)
            *(float2*)(out + (size_t)row0 * NCLASS + c) =
                make_float2(acc[nt][0] - lse0, acc[nt][1] - lse0);
        if (row1 < N_NODES)
            *(float2*)(out + (size_t)row1 * NCLASS + c) =
                make_float2(acc[nt][2] - lse1, acc[nt][3] - lse1);
    }
}

// ---------------------------------------------------------------------------
extern "C" void kernel_launch(void* const* d_in, const int* in_sizes, int n_in,
                              void* d_out, int out_size)
{
    const float* x    = (const float*)d_in[0];
    const int*   rows = (const int*)  d_in[1];
    const int*   cols = (const int*)  d_in[2];
    const float* vals = (const float*)d_in[3];
    const float* W1   = (const float*)d_in[4];
    const float* b1   = (const float*)d_in[5];
    const float* W2   = (const float*)d_in[6];
    const float* b2   = (const float*)d_in[7];
    float* out = (float*)d_out;

    float *h0, *h1;
    cudaGetSymbolAddress((void**)&h0, g_h0);
    cudaGetSymbolAddress((void**)&h1, g_h1);

    cudaFuncSetAttribute(gemm1_mma_kernel, cudaFuncAttributeMaxDynamicSharedMemorySize, SMEM_G1_BYTES);
    cudaFuncSetAttribute(gemm2_mma_kernel, cudaFuncAttributeMaxDynamicSharedMemorySize, SMEM_G2_BYTES);

    // 0) prep
    prep_w1_kernel<<<(NHID * NFEAT / 2 + 255) / 256, 256>>>(W1);
    prep_w2_kernel<<<(NCLASS * NHID / 2 + 255) / 256, 256>>>(W2);
    rowptr_kernel<<<(N_EDGES + 255) / 256, 256>>>(rows);

    // 1) h0 = X @ W1
    gemm1_mma_kernel<<<(N_NODES + 127) / 128, 256, SMEM_G1_BYTES>>>(x, h0);

    // 2) h1 = relu(A @ h0 + b1)
    const int spmm_blocks = (N_NODES * 32 + 255) / 256;
    spmm_kernel<true><<<spmm_blocks, 256>>>(cols, vals, h0, b1, h1);

    // 3) h0 <- A @ h1
    spmm_kernel<false><<<spmm_blocks, 256>>>(cols, vals, h1, b1, h0);

    // 4) out = logsoftmax(h0 @ W2 + b2)
    gemm2_mma_kernel<<<(N_NODES + 63) / 64, 128, SMEM_G2_BYTES>>>(h0, b2, out);
}